// round 3
// baseline (speedup 1.0000x reference)
#include <cuda_runtime.h>
#include <cuda_bf16.h>
#include <math.h>

#define NN 50000
#define EE 800000
#define ET (EE + NN)
#define FIN 128
#define HID 128
#define HEADS 4
#define HO (HEADS * HID)   // 512
#define GP 512             // pooling groups

// ---------------- scratch (__device__ globals; no allocation) ----------------
__device__ float g_h1pre[(size_t)NN * HO];
__device__ float g_h1[(size_t)NN * HO];
__device__ float g_h2pre[(size_t)NN * HID];
__device__ float g_h2[(size_t)NN * HID];
__device__ float g_as1[(size_t)NN * HEADS];
__device__ float g_ad1[(size_t)NN * HEADS];
__device__ float g_as2[NN];
__device__ float g_ad2[NN];
__device__ int g_deg[NN];
__device__ int g_rowptr[NN + 1];
__device__ int g_cursor[NN];
__device__ int g_col[ET];

// ---------------- CSR build ----------------
__global__ void k_init_deg(int* deg) {
    int i = blockIdx.x * blockDim.x + threadIdx.x;
    if (i < NN) deg[i] = 1;  // self loop
}

__global__ void k_hist(const int* __restrict__ ei, int* deg) {
    int e = blockIdx.x * blockDim.x + threadIdx.x;
    if (e < EE) atomicAdd(&deg[ei[EE + e]], 1);  // dst row
}

__global__ void k_scan(const int* __restrict__ deg, int* __restrict__ rowptr, int n) {
    __shared__ int tmp[1024];
    __shared__ int s_carry;
    int t = threadIdx.x;
    if (t == 0) { s_carry = 0; rowptr[0] = 0; }
    __syncthreads();
    for (int base = 0; base < n; base += 1024) {
        int v = (base + t < n) ? deg[base + t] : 0;
        tmp[t] = v;
        __syncthreads();
        for (int off = 1; off < 1024; off <<= 1) {
            int x = (t >= off) ? tmp[t - off] : 0;
            __syncthreads();
            tmp[t] += x;
            __syncthreads();
        }
        int incl = tmp[t];
        int c = s_carry;
        if (base + t < n) rowptr[base + t + 1] = c + incl;
        int total = tmp[1023];
        __syncthreads();
        if (t == 0) s_carry = c + total;
        __syncthreads();
    }
}

__global__ void k_copy_cursor(const int* __restrict__ rowptr, int* cursor) {
    int i = blockIdx.x * blockDim.x + threadIdx.x;
    if (i < NN) cursor[i] = rowptr[i];
}

__global__ void k_scatter(const int* __restrict__ ei, int* cursor, int* col) {
    int e = blockIdx.x * blockDim.x + threadIdx.x;
    if (e < EE) {
        int d = ei[EE + e];
        int p = atomicAdd(&cursor[d], 1);
        col[p] = ei[e];  // src
    }
}

__global__ void k_self(int* cursor, int* col) {
    int n = blockIdx.x * blockDim.x + threadIdx.x;
    if (n < NN) {
        int p = atomicAdd(&cursor[n], 1);
        col[p] = n;
    }
}

// ---------------- SGEMM: C[M,N] = A[M,K] @ B[K,N] ----------------
#define BM 128
#define BN 64
#define BK 16
#define TM 8
#define TN 4
__global__ __launch_bounds__(256) void gemm_k(const float* __restrict__ A,
                                              const float* __restrict__ B,
                                              float* __restrict__ C,
                                              int M, int N, int K) {
    __shared__ float As[BK][BM + 4];
    __shared__ float Bs[BK][BN];
    const int tid = threadIdx.x;
    const int bm = blockIdx.y * BM;
    const int bn = blockIdx.x * BN;
    const int tx = tid & 15;   // N dir
    const int ty = tid >> 4;   // M dir
    float acc[TM][TN];
#pragma unroll
    for (int i = 0; i < TM; i++)
#pragma unroll
        for (int j = 0; j < TN; j++) acc[i][j] = 0.f;

    for (int k0 = 0; k0 < K; k0 += BK) {
        // A tile: BM x BK, each thread 2 x float4
#pragma unroll
        for (int i = 0; i < 2; i++) {
            int p = tid * 2 + i;          // 0..511
            int m = p >> 2, cv = p & 3;
            float4 v = make_float4(0.f, 0.f, 0.f, 0.f);
            int gm = bm + m;
            if (gm < M) v = *(const float4*)&A[(size_t)gm * K + k0 + cv * 4];
            As[cv * 4 + 0][m] = v.x;
            As[cv * 4 + 1][m] = v.y;
            As[cv * 4 + 2][m] = v.z;
            As[cv * 4 + 3][m] = v.w;
        }
        // B tile: BK x BN, each thread 1 x float4
        {
            int kk = tid >> 4, cv = tid & 15;
            float4 v = *(const float4*)&B[(size_t)(k0 + kk) * N + bn + cv * 4];
            *(float4*)&Bs[kk][cv * 4] = v;
        }
        __syncthreads();
#pragma unroll
        for (int k = 0; k < BK; k++) {
            float4 a0 = *(const float4*)&As[k][ty * TM];
            float4 a1 = *(const float4*)&As[k][ty * TM + 4];
            float4 b0 = *(const float4*)&Bs[k][tx * TN];
            float ra[TM] = {a0.x, a0.y, a0.z, a0.w, a1.x, a1.y, a1.z, a1.w};
            float rb[TN] = {b0.x, b0.y, b0.z, b0.w};
#pragma unroll
            for (int i = 0; i < TM; i++)
#pragma unroll
                for (int j = 0; j < TN; j++) acc[i][j] = fmaf(ra[i], rb[j], acc[i][j]);
        }
        __syncthreads();
    }
#pragma unroll
    for (int i = 0; i < TM; i++) {
        int gm = bm + ty * TM + i;
        if (gm < M) {
            float4 v = make_float4(acc[i][0], acc[i][1], acc[i][2], acc[i][3]);
            *(float4*)&C[(size_t)gm * N + bn + tx * TN] = v;
        }
    }
}

// ---------------- attention coefficients ----------------
__global__ void k_attn1(const float* __restrict__ h, const float* __restrict__ a_src,
                        const float* __restrict__ a_dst, float* asrc, float* adst) {
    int n = blockIdx.x, t = threadIdx.x;  // 128 threads, 4 warps
    __shared__ float wps[4][HEADS], wpd[4][HEADS];
    const float* hp = h + (size_t)n * HO;
#pragma unroll
    for (int hd = 0; hd < HEADS; hd++) {
        float v = hp[hd * HID + t];
        float ps = v * a_src[hd * HID + t];
        float pd = v * a_dst[hd * HID + t];
        for (int o = 16; o; o >>= 1) {
            ps += __shfl_xor_sync(0xffffffffu, ps, o);
            pd += __shfl_xor_sync(0xffffffffu, pd, o);
        }
        if ((t & 31) == 0) { wps[t >> 5][hd] = ps; wpd[t >> 5][hd] = pd; }
    }
    __syncthreads();
    if (t < HEADS) {
        asrc[n * HEADS + t] = wps[0][t] + wps[1][t] + wps[2][t] + wps[3][t];
        adst[n * HEADS + t] = wpd[0][t] + wpd[1][t] + wpd[2][t] + wpd[3][t];
    }
}

__global__ void k_attn2(const float* __restrict__ h, const float* __restrict__ a_src,
                        const float* __restrict__ a_dst, float* asrc, float* adst) {
    int n = blockIdx.x, t = threadIdx.x;  // 128
    __shared__ float wps[4], wpd[4];
    float v = h[(size_t)n * HID + t];
    float ps = v * a_src[t];
    float pd = v * a_dst[t];
    for (int o = 16; o; o >>= 1) {
        ps += __shfl_xor_sync(0xffffffffu, ps, o);
        pd += __shfl_xor_sync(0xffffffffu, pd, o);
    }
    if ((t & 31) == 0) { wps[t >> 5] = ps; wpd[t >> 5] = pd; }
    __syncthreads();
    if (t == 0) {
        asrc[n] = wps[0] + wps[1] + wps[2] + wps[3];
        adst[n] = wpd[0] + wpd[1] + wpd[2] + wpd[3];
    }
}

__device__ __forceinline__ float lrelu(float x) { return x > 0.f ? x : 0.2f * x; }
__device__ __forceinline__ float elu1(float x) { return x > 0.f ? x : expm1f(x); }

// ---------------- GAT aggregation, layer 1 (4 heads, C=128) ----------------
__global__ __launch_bounds__(256) void k_agg1(const float* __restrict__ hmat,
                                              const float* __restrict__ asrc,
                                              const float* __restrict__ adst,
                                              const int* __restrict__ rowptr,
                                              const int* __restrict__ col,
                                              const float* __restrict__ bias,
                                              float* __restrict__ outm) {
    const int n = blockIdx.x;
    const int t = threadIdx.x;  // 256
    const int e0 = rowptr[n], e1 = rowptr[n + 1];
    __shared__ float s_ad[4], s_m[4], s_d[4];
    __shared__ float wred[8][4];
    __shared__ float w_sh[128][4];
    __shared__ int src_sh[128];
    if (t < 4) s_ad[t] = adst[n * 4 + t];
    __syncthreads();

    // pass 1: per-head max logit
    float m0 = -1e30f, m1 = -1e30f, m2 = -1e30f, m3 = -1e30f;
    for (int e = e0 + t; e < e1; e += 256) {
        int s = col[e];
        float4 av = *(const float4*)(asrc + (size_t)s * 4);
        m0 = fmaxf(m0, lrelu(av.x + s_ad[0]));
        m1 = fmaxf(m1, lrelu(av.y + s_ad[1]));
        m2 = fmaxf(m2, lrelu(av.z + s_ad[2]));
        m3 = fmaxf(m3, lrelu(av.w + s_ad[3]));
    }
    for (int o = 16; o; o >>= 1) {
        m0 = fmaxf(m0, __shfl_xor_sync(0xffffffffu, m0, o));
        m1 = fmaxf(m1, __shfl_xor_sync(0xffffffffu, m1, o));
        m2 = fmaxf(m2, __shfl_xor_sync(0xffffffffu, m2, o));
        m3 = fmaxf(m3, __shfl_xor_sync(0xffffffffu, m3, o));
    }
    if ((t & 31) == 0) {
        wred[t >> 5][0] = m0; wred[t >> 5][1] = m1;
        wred[t >> 5][2] = m2; wred[t >> 5][3] = m3;
    }
    __syncthreads();
    if (t < 4) {
        float mm = -1e30f;
        for (int w = 0; w < 8; w++) mm = fmaxf(mm, wred[w][t]);
        s_m[t] = mm;
    }
    __syncthreads();

    // pass 2: staged exp weights + weighted gather + denom
    float acc0 = 0.f, acc1 = 0.f;
    float d0 = 0.f, d1 = 0.f, d2 = 0.f, d3 = 0.f;
    const int h0 = t >> 7;          // 0 or 1
    const int h1 = 2 + (t >> 7);    // 2 or 3
    for (int base = e0; base < e1; base += 128) {
        int cnt = min(128, e1 - base);
        __syncthreads();
        if (t < cnt) {
            int s = col[base + t];
            src_sh[t] = s;
            float4 av = *(const float4*)(asrc + (size_t)s * 4);
            float w;
            w = __expf(lrelu(av.x + s_ad[0]) - s_m[0]); w_sh[t][0] = w; d0 += w;
            w = __expf(lrelu(av.y + s_ad[1]) - s_m[1]); w_sh[t][1] = w; d1 += w;
            w = __expf(lrelu(av.z + s_ad[2]) - s_m[2]); w_sh[t][2] = w; d2 += w;
            w = __expf(lrelu(av.w + s_ad[3]) - s_m[3]); w_sh[t][3] = w; d3 += w;
        }
        __syncthreads();
#pragma unroll 2
        for (int j = 0; j < cnt; j++) {
            const float* hp = hmat + (size_t)src_sh[j] * HO;
            acc0 += w_sh[j][h0] * __ldg(hp + t);
            acc1 += w_sh[j][h1] * __ldg(hp + t + 256);
        }
    }
    // reduce denominators
    for (int o = 16; o; o >>= 1) {
        d0 += __shfl_xor_sync(0xffffffffu, d0, o);
        d1 += __shfl_xor_sync(0xffffffffu, d1, o);
        d2 += __shfl_xor_sync(0xffffffffu, d2, o);
        d3 += __shfl_xor_sync(0xffffffffu, d3, o);
    }
    __syncthreads();
    if ((t & 31) == 0) {
        wred[t >> 5][0] = d0; wred[t >> 5][1] = d1;
        wred[t >> 5][2] = d2; wred[t >> 5][3] = d3;
    }
    __syncthreads();
    if (t < 4) {
        float dd = 0.f;
        for (int w = 0; w < 8; w++) dd += wred[w][t];
        s_d[t] = dd;
    }
    __syncthreads();
    float r0 = acc0 / s_d[h0] + bias[t];
    float r1 = acc1 / s_d[h1] + bias[t + 256];
    outm[(size_t)n * HO + t] = elu1(r0);
    outm[(size_t)n * HO + 256 + t] = elu1(r1);
}

// ---------------- GAT aggregation, layer 2 (1 head, C=128) ----------------
__global__ __launch_bounds__(128) void k_agg2(const float* __restrict__ hmat,
                                              const float* __restrict__ asrc,
                                              const float* __restrict__ adst,
                                              const int* __restrict__ rowptr,
                                              const int* __restrict__ col,
                                              const float* __restrict__ bias,
                                              float* __restrict__ outm) {
    const int n = blockIdx.x;
    const int t = threadIdx.x;  // 128
    const int e0 = rowptr[n], e1 = rowptr[n + 1];
    __shared__ float wred[4];
    __shared__ float s_m, s_d;
    __shared__ float w_sh[128];
    __shared__ int src_sh[128];
    const float ad = adst[n];

    float m0 = -1e30f;
    for (int e = e0 + t; e < e1; e += 128)
        m0 = fmaxf(m0, lrelu(asrc[col[e]] + ad));
    for (int o = 16; o; o >>= 1) m0 = fmaxf(m0, __shfl_xor_sync(0xffffffffu, m0, o));
    if ((t & 31) == 0) wred[t >> 5] = m0;
    __syncthreads();
    if (t == 0) s_m = fmaxf(fmaxf(wred[0], wred[1]), fmaxf(wred[2], wred[3]));
    __syncthreads();

    float acc = 0.f, d0 = 0.f;
    for (int base = e0; base < e1; base += 128) {
        int cnt = min(128, e1 - base);
        __syncthreads();
        if (t < cnt) {
            int s = col[base + t];
            src_sh[t] = s;
            float w = __expf(lrelu(asrc[s] + ad) - s_m);
            w_sh[t] = w;
            d0 += w;
        }
        __syncthreads();
#pragma unroll 4
        for (int j = 0; j < cnt; j++)
            acc += w_sh[j] * __ldg(hmat + (size_t)src_sh[j] * HID + t);
    }
    for (int o = 16; o; o >>= 1) d0 += __shfl_xor_sync(0xffffffffu, d0, o);
    __syncthreads();
    if ((t & 31) == 0) wred[t >> 5] = d0;
    __syncthreads();
    if (t == 0) s_d = wred[0] + wred[1] + wred[2] + wred[3];
    __syncthreads();
    float r = acc / s_d + bias[t];
    outm[(size_t)n * HID + t] = elu1(r);
}

// ---------------- pooling + linear head ----------------
__device__ __forceinline__ int lbound(const int* a, int n, int v) {
    int lo = 0, hi = n;
    while (lo < hi) {
        int mid = (lo + hi) >> 1;
        if (a[mid] < v) lo = mid + 1; else hi = mid;
    }
    return lo;
}

__global__ void k_pool(const float* __restrict__ h2, const int* __restrict__ batch,
                       const float* __restrict__ Wl, const float* __restrict__ bl,
                       float* __restrict__ out) {
    int g = blockIdx.x, t = threadIdx.x;  // 128
    __shared__ float wred[4];
    int lo = lbound(batch, NN, g);
    int hi = lbound(batch, NN, g + 1);
    float s = 0.f;
    for (int i = lo; i < hi; i++) s += h2[(size_t)i * HID + t];
    float cnt = (float)(hi - lo);
    if (cnt < 1.f) cnt = 1.f;
    float p = (s / cnt) * Wl[t];
    for (int o = 16; o; o >>= 1) p += __shfl_xor_sync(0xffffffffu, p, o);
    if ((t & 31) == 0) wred[t >> 5] = p;
    __syncthreads();
    if (t == 0) out[g] = wred[0] + wred[1] + wred[2] + wred[3] + bl[0];
}

// ---------------- launcher ----------------
extern "C" void kernel_launch(void* const* d_in, const int* in_sizes, int n_in,
                              void* d_out, int out_size) {
    const float* x      = (const float*)d_in[0];
    const int*   ei     = (const int*)d_in[1];
    const int*   batch  = (const int*)d_in[2];
    const float* W1     = (const float*)d_in[3];
    const float* a_src1 = (const float*)d_in[4];
    const float* a_dst1 = (const float*)d_in[5];
    const float* b1     = (const float*)d_in[6];
    const float* W2     = (const float*)d_in[7];
    const float* a_src2 = (const float*)d_in[8];
    const float* a_dst2 = (const float*)d_in[9];
    const float* b2     = (const float*)d_in[10];
    const float* Wl     = (const float*)d_in[11];
    const float* bl     = (const float*)d_in[12];
    float* out = (float*)d_out;

    float *h1pre, *h1, *h2pre, *h2, *as1, *ad1, *as2, *ad2;
    int *deg, *rowptr, *cursor, *colv;
    cudaGetSymbolAddress((void**)&h1pre, g_h1pre);
    cudaGetSymbolAddress((void**)&h1, g_h1);
    cudaGetSymbolAddress((void**)&h2pre, g_h2pre);
    cudaGetSymbolAddress((void**)&h2, g_h2);
    cudaGetSymbolAddress((void**)&as1, g_as1);
    cudaGetSymbolAddress((void**)&ad1, g_ad1);
    cudaGetSymbolAddress((void**)&as2, g_as2);
    cudaGetSymbolAddress((void**)&ad2, g_ad2);
    cudaGetSymbolAddress((void**)&deg, g_deg);
    cudaGetSymbolAddress((void**)&rowptr, g_rowptr);
    cudaGetSymbolAddress((void**)&cursor, g_cursor);
    cudaGetSymbolAddress((void**)&colv, g_col);

    // CSR build (dst-major)
    k_init_deg<<<(NN + 255) / 256, 256>>>(deg);
    k_hist<<<(EE + 255) / 256, 256>>>(ei, deg);
    k_scan<<<1, 1024>>>(deg, rowptr, NN);
    k_copy_cursor<<<(NN + 255) / 256, 256>>>(rowptr, cursor);
    k_scatter<<<(EE + 255) / 256, 256>>>(ei, cursor, colv);
    k_self<<<(NN + 255) / 256, 256>>>(cursor, colv);

    // layer 1
    gemm_k<<<dim3(HO / BN, (NN + BM - 1) / BM), 256>>>(x, W1, h1pre, NN, HO, FIN);
    k_attn1<<<NN, 128>>>(h1pre, a_src1, a_dst1, as1, ad1);
    k_agg1<<<NN, 256>>>(h1pre, as1, ad1, rowptr, colv, b1, h1);

    // layer 2
    gemm_k<<<dim3(HID / BN, (NN + BM - 1) / BM), 256>>>(h1, W2, h2pre, NN, HID, HO);
    k_attn2<<<NN, 128>>>(h2pre, a_src2, a_dst2, as2, ad2);
    k_agg2<<<NN, 128>>>(h2pre, as2, ad2, rowptr, colv, b2, h2);

    // pool + head
    k_pool<<<GP, 128>>>(h2, batch, Wl, bl, out);
}